// round 2
// baseline (speedup 1.0000x reference)
#include <cuda_runtime.h>
#include <math.h>

// Problem constants
#define B_   128
#define T_   512
#define I_   64
#define H_   512
#define L_   64
#define DEC_ 100

// ---------------- scratch (device globals; no allocation allowed) ----------------
__device__ float g_hA[B_ * H_];
__device__ float g_hB[B_ * H_];
__device__ float g_c [B_ * H_];
__device__ float g_z [B_ * L_];
__device__ float g_x [B_ * L_];

__device__ __forceinline__ float sigf(float v) { return 1.0f / (1.0f + expf(-v)); }

// ---------------- fused LSTM step ----------------
// Block computes a [BM batch x BJ hidden] tile covering all 4 gates (BN=4*BJ gate
// columns), then performs the cell update for its tile. h is ping-ponged between
// two buffers (h_in read fully, h_out written only for this block's slice).
#define BM 64
#define BJ 8
#define BN 32
#define KT 64
#define NT 128

__global__ __launch_bounds__(NT)
void lstm_step(const float* __restrict__ x, int ldx,
               const float* __restrict__ Wih,   // [4H, 64]
               const float* __restrict__ Whh,   // [4H, 512]
               const float* __restrict__ bih,
               const float* __restrict__ bhh,
               const float* __restrict__ h_in,
               float* __restrict__ h_out,
               float* __restrict__ c)
{
    __shared__ float As[BM][KT + 1];   // odd stride -> conflict-free broadcast reads
    __shared__ float Bs[BN][KT + 1];

    const int tid = threadIdx.x;
    const int j0  = blockIdx.x * BJ;   // hidden slice start
    const int m0  = blockIdx.y * BM;   // batch slice start
    const int ty  = tid >> 3;          // 0..15  (m dimension)
    const int tx  = tid & 7;           // 0..7   (n dimension)

    float acc[4][4];
#pragma unroll
    for (int i = 0; i < 4; ++i)
#pragma unroll
        for (int j = 0; j < 4; ++j) acc[i][j] = 0.0f;

    // Tile 0: input part (K = I_ = 64), tiles 1..8: recurrent part (K = 512)
    const int NTILES = 1 + H_ / KT;
    for (int tt = 0; tt < NTILES; ++tt) {
        const float* Ap;
        const float* Bp;
        int lda, ldb, k0;
        if (tt == 0) { Ap = x;    lda = ldx; Bp = Wih; ldb = I_; k0 = 0; }
        else         { Ap = h_in; lda = H_;  Bp = Whh; ldb = H_; k0 = (tt - 1) * KT; }

        // Load A tile [BM x KT], coalesced along k
        for (int idx = tid; idx < BM * KT; idx += NT) {
            int m = idx >> 6, k = idx & 63;
            As[m][k] = Ap[(m0 + m) * lda + k0 + k];
        }
        // Load B tile: BN gate rows (4 gates x BJ hidden), coalesced along k
        for (int idx = tid; idx < BN * KT; idx += NT) {
            int r = idx >> 6, k = idx & 63;
            int row = ((r >> 3) * H_) + j0 + (r & 7);
            Bs[r][k] = Bp[row * ldb + k0 + k];
        }
        __syncthreads();

#pragma unroll 8
        for (int k = 0; k < KT; ++k) {
            float a0 = As[ty * 4 + 0][k];
            float a1 = As[ty * 4 + 1][k];
            float a2 = As[ty * 4 + 2][k];
            float a3 = As[ty * 4 + 3][k];
            float b0 = Bs[tx * 4 + 0][k];
            float b1 = Bs[tx * 4 + 1][k];
            float b2 = Bs[tx * 4 + 2][k];
            float b3 = Bs[tx * 4 + 3][k];
            acc[0][0] += a0 * b0; acc[0][1] += a0 * b1; acc[0][2] += a0 * b2; acc[0][3] += a0 * b3;
            acc[1][0] += a1 * b0; acc[1][1] += a1 * b1; acc[1][2] += a1 * b2; acc[1][3] += a1 * b3;
            acc[2][0] += a2 * b0; acc[2][1] += a2 * b1; acc[2][2] += a2 * b2; acc[2][3] += a2 * b3;
            acc[3][0] += a3 * b0; acc[3][1] += a3 * b1; acc[3][2] += a3 * b2; acc[3][3] += a3 * b3;
        }
        __syncthreads();
    }

    // Stage C tile through smem (reuse As) so each thread can gather its 4 gates
#pragma unroll
    for (int i = 0; i < 4; ++i)
#pragma unroll
        for (int j = 0; j < 4; ++j)
            As[ty * 4 + i][tx * 4 + j] = acc[i][j];
    __syncthreads();

    // Cell update: 512 (b, j) cells per block, 4 per thread
#pragma unroll
    for (int w = 0; w < 4; ++w) {
        int idx = w * NT + tid;        // 0..511
        int m  = idx >> 3;             // 0..63
        int jj = idx & 7;              // 0..7
        int b = m0 + m;
        int j = j0 + jj;
        float gi = As[m][jj]       + bih[0 * H_ + j] + bhh[0 * H_ + j];
        float gf = As[m][8  + jj]  + bih[1 * H_ + j] + bhh[1 * H_ + j];
        float gg = As[m][16 + jj]  + bih[2 * H_ + j] + bhh[2 * H_ + j];
        float go = As[m][24 + jj]  + bih[3 * H_ + j] + bhh[3 * H_ + j];
        float c_old = c[b * H_ + j];
        float cn = sigf(gf) * c_old + sigf(gi) * tanhf(gg);
        float hn = sigf(go) * tanhf(cn);
        c[b * H_ + j]     = cn;
        h_out[b * H_ + j] = hn;
    }
}

// ---------------- zero-init h and c ----------------
__global__ void zero_kernel(float* __restrict__ h, float* __restrict__ c)
{
    int idx = blockIdx.x * blockDim.x + threadIdx.x;
    if (idx < B_ * H_) { h[idx] = 0.0f; c[idx] = 0.0f; }
}

// ---------------- VAE: mean / log_var / z ----------------
__global__ void vae_kernel(const float* __restrict__ h,
                           const float* __restrict__ Wm, const float* __restrict__ bm,
                           const float* __restrict__ Wv, const float* __restrict__ bv,
                           const float* __restrict__ eps,
                           float* __restrict__ out_mean, float* __restrict__ out_lv,
                           float* __restrict__ z)
{
    int w    = (blockIdx.x * blockDim.x + threadIdx.x) >> 5;
    int lane = threadIdx.x & 31;
    if (w >= B_ * L_) return;
    int b = w >> 6, l = w & 63;
    const float* hb = h + b * H_;
    const float* wm = Wm + l * H_;
    const float* wv = Wv + l * H_;
    float sm = 0.0f, sv = 0.0f;
#pragma unroll 4
    for (int k = lane; k < H_; k += 32) {
        float hv = hb[k];
        sm += hv * wm[k];
        sv += hv * wv[k];
    }
#pragma unroll
    for (int o = 16; o > 0; o >>= 1) {
        sm += __shfl_down_sync(0xffffffffu, sm, o);
        sv += __shfl_down_sync(0xffffffffu, sv, o);
    }
    if (lane == 0) {
        sm += bm[l];
        sv += bv[l];
        out_mean[b * L_ + l] = sm;
        out_lv  [b * L_ + l] = sv;
        z[b * L_ + l] = sm + eps[b * L_ + l] * expf(0.5f * sv);
    }
}

// ---------------- decoder init: h0 = z @ W_init^T + b_init; c = 0; x0 = 0 ----------------
__global__ void init_dec(const float* __restrict__ z,
                         const float* __restrict__ Wi, const float* __restrict__ bi,
                         float* __restrict__ h, float* __restrict__ c, float* __restrict__ x)
{
    int idx = blockIdx.x * blockDim.x + threadIdx.x;   // 0..65535
    if (idx >= B_ * H_) return;
    int b = idx >> 9, j = idx & 511;
    const float* zb = z + b * L_;
    const float* wr = Wi + j * L_;
    float s = bi[j];
#pragma unroll 16
    for (int k = 0; k < L_; ++k) s += zb[k] * wr[k];
    h[idx] = s;
    c[idx] = 0.0f;
    if (j < L_) x[b * L_ + j] = 0.0f;
}

// ---------------- decoder output projection: x_hat = h @ W_out^T + b_out ----------------
__global__ void out_proj(const float* __restrict__ h,
                         const float* __restrict__ Wo, const float* __restrict__ bo,
                         float* __restrict__ xbuf, float* __restrict__ out_xhat, int s)
{
    int w    = (blockIdx.x * blockDim.x + threadIdx.x) >> 5;
    int lane = threadIdx.x & 31;
    if (w >= B_ * I_) return;
    int b = w >> 6, i = w & 63;
    const float* hb = h + b * H_;
    const float* wr = Wo + i * H_;
    float sum = 0.0f;
#pragma unroll 4
    for (int k = lane; k < H_; k += 32) sum += hb[k] * wr[k];
#pragma unroll
    for (int o = 16; o > 0; o >>= 1) sum += __shfl_down_sync(0xffffffffu, sum, o);
    if (lane == 0) {
        float v = sum + bo[i];
        xbuf[b * I_ + i] = v;
        out_xhat[(b * DEC_ + s) * I_ + i] = v;
    }
}

// ---------------- launch ----------------
extern "C" void kernel_launch(void* const* d_in, const int* in_sizes, int n_in,
                              void* d_out, int out_size)
{
    (void)in_sizes; (void)n_in; (void)out_size;

    const float* seq    = (const float*)d_in[0];
    // d_in[1] = seq_lengths (unused by reference)
    const float* eps    = (const float*)d_in[2];
    const float* Wih_e  = (const float*)d_in[3];
    const float* Whh_e  = (const float*)d_in[4];
    const float* bih_e  = (const float*)d_in[5];
    const float* bhh_e  = (const float*)d_in[6];
    const float* Wm     = (const float*)d_in[7];
    const float* bm     = (const float*)d_in[8];
    const float* Wv     = (const float*)d_in[9];
    const float* bv     = (const float*)d_in[10];
    const float* Wi     = (const float*)d_in[11];
    const float* bi     = (const float*)d_in[12];
    const float* Wih_d  = (const float*)d_in[13];
    const float* Whh_d  = (const float*)d_in[14];
    const float* bih_d  = (const float*)d_in[15];
    const float* bhh_d  = (const float*)d_in[16];
    const float* Wo     = (const float*)d_in[17];
    const float* bo     = (const float*)d_in[18];

    float* out       = (float*)d_out;
    float* out_xhat  = out;                         // [B, 100, I]
    float* out_mean  = out + B_ * DEC_ * I_;        // [B, L]
    float* out_lv    = out_mean + B_ * L_;          // [B, L]

    float *hA, *hB, *cptr, *zptr, *xptr;
    cudaGetSymbolAddress((void**)&hA,   g_hA);
    cudaGetSymbolAddress((void**)&hB,   g_hB);
    cudaGetSymbolAddress((void**)&cptr, g_c);
    cudaGetSymbolAddress((void**)&zptr, g_z);
    cudaGetSymbolAddress((void**)&xptr, g_x);

    dim3 sgrid(H_ / BJ, B_ / BM);   // (64, 2) = 128 blocks

    // ---- encoder ----
    zero_kernel<<<(B_ * H_ + 255) / 256, 256>>>(hA, cptr);
    const float* hin = hA;
    float*       hout = hB;
    for (int t = 0; t < T_; ++t) {
        lstm_step<<<sgrid, NT>>>(seq + t * I_, T_ * I_,
                                 Wih_e, Whh_e, bih_e, bhh_e,
                                 hin, hout, cptr);
        const float* tmp = hin; hin = hout; hout = (float*)tmp;
    }
    // final h_n is in `hin`

    // ---- VAE ----
    vae_kernel<<<(B_ * L_ * 32) / 256, 256>>>(hin, Wm, bm, Wv, bv, eps,
                                              out_mean, out_lv, zptr);

    // ---- decoder init ----
    init_dec<<<(B_ * H_ + 255) / 256, 256>>>(zptr, Wi, bi, hA, cptr, xptr);

    // ---- decoder loop ----
    hin = hA; hout = hB;
    for (int s = 0; s < DEC_; ++s) {
        lstm_step<<<sgrid, NT>>>(xptr, I_,
                                 Wih_d, Whh_d, bih_d, bhh_d,
                                 hin, hout, cptr);
        out_proj<<<(B_ * I_ * 32) / 256, 256>>>(hout, Wo, bo, xptr, out_xhat, s);
        const float* tmp = hin; hin = hout; hout = (float*)tmp;
    }
}

// round 3
// speedup vs baseline: 2.0230x; 2.0230x over previous
#include <cuda_runtime.h>
#include <math.h>

// Problem constants
#define B_   128
#define T_   512
#define I_   64
#define H_   512
#define L_   64
#define DEC_ 100

typedef unsigned long long ull;

// ---------------- scratch (device globals; no allocation allowed) ----------------
__device__ float g_hA[B_ * H_];
__device__ float g_hB[B_ * H_];
__device__ float g_c [B_ * H_];
__device__ float g_z [B_ * L_];
__device__ float g_x [B_ * L_];

__device__ __forceinline__ float sigf(float v) { return 1.0f / (1.0f + expf(-v)); }

// Packed dual-FMA: acc.{lo,hi} += a.{lo,hi} * b.{lo,hi}   (sm_10x f32x2 pipe, rt=2
// per SMSP for 2 MACs -> 2x the scalar FFMA-3reg throughput)
__device__ __forceinline__ void ffma2(ull& d, ull a, ull b) {
    asm("fma.rn.f32x2 %0, %1, %2, %0;" : "+l"(d) : "l"(a), "l"(b));
}

// ---------------- fused LSTM step ----------------
// Block tile: BM=64 batch x BN=32 gate-cols (all 4 gates of BJ=8 hidden units).
// 256 threads, microtile 2m x 4n, K packed in pairs for f32x2 FMAs.
// Grid (64 hidden slices, 2 batch halves) = 128 blocks.
#define BM 64
#define BJ 8
#define BN 32
#define KT 64
#define NT 256
#define ASTR 66   // padded row stride (floats): 264B -> 8B-aligned k-pairs

__global__ __launch_bounds__(NT)
void lstm_step(const float* __restrict__ x, int ldx,
               const float* __restrict__ Wih,   // [4H, I]
               const float* __restrict__ Whh,   // [4H, H]
               const float* __restrict__ bih,
               const float* __restrict__ bhh,
               const float* __restrict__ h_in,
               float* __restrict__ h_out,
               float* __restrict__ c)
{
    __shared__ float As[BM * ASTR];   // A tile [m][k]
    __shared__ float Bs[BN * ASTR];   // B tile [gatecol][k]

    const int tid = threadIdx.x;
    const int j0  = blockIdx.x * BJ;   // hidden slice start
    const int m0  = blockIdx.y * BM;   // batch slice start
    const int tx  = tid & 7;           // n group: 8 x 4 cols
    const int ty  = tid >> 3;          // m group: 32 x 2 rows

    ull acc[2][4];
#pragma unroll
    for (int i = 0; i < 2; ++i)
#pragma unroll
        for (int j = 0; j < 4; ++j) acc[i][j] = 0ull;

    const int ra0 = (ty * 2) * ASTR;
    const int ra1 = ra0 + ASTR;
    const int rb0 = (tx * 4) * ASTR;

    // Tile 0: input part (K = I_ = 64); tiles 1..8: recurrent part (K = 512)
    const int NTILES = 1 + H_ / KT;
    for (int tt = 0; tt < NTILES; ++tt) {
        const float* Ap;
        const float* Bp;
        int lda, ldb, k0;
        if (tt == 0) { Ap = x;    lda = ldx; Bp = Wih; ldb = I_; k0 = 0; }
        else         { Ap = h_in; lda = H_;  Bp = Whh; ldb = H_; k0 = (tt - 1) * KT; }

        // Load A tile [BM x KT]: float4 gmem reads, float2 smem writes
        {
            // 64 rows x 16 float4 = 1024 quads, 4 per thread
#pragma unroll
            for (int it = 0; it < 4; ++it) {
                int idx = tid + it * NT;
                int m = idx >> 4, k4 = idx & 15;
                float4 v = *(const float4*)&Ap[(m0 + m) * lda + k0 + k4 * 4];
                float2* dst = (float2*)&As[m * ASTR + k4 * 4];
                dst[0] = make_float2(v.x, v.y);
                dst[1] = make_float2(v.z, v.w);
            }
        }
        // Load B tile [BN x KT]: 32 rows x 16 quads = 512, 2 per thread
        {
#pragma unroll
            for (int it = 0; it < 2; ++it) {
                int idx = tid + it * NT;
                int r = idx >> 4, k4 = idx & 15;
                int row = ((r >> 3) * H_) + j0 + (r & 7);
                float4 v = *(const float4*)&Bp[row * ldb + k0 + k4 * 4];
                float2* dst = (float2*)&Bs[r * ASTR + k4 * 4];
                dst[0] = make_float2(v.x, v.y);
                dst[1] = make_float2(v.z, v.w);
            }
        }
        __syncthreads();

#pragma unroll
        for (int kp = 0; kp < KT / 2; ++kp) {
            ull a0 = *(const ull*)&As[ra0 + 2 * kp];
            ull a1 = *(const ull*)&As[ra1 + 2 * kp];
            ull b0 = *(const ull*)&Bs[rb0 + 0 * ASTR + 2 * kp];
            ull b1 = *(const ull*)&Bs[rb0 + 1 * ASTR + 2 * kp];
            ull b2 = *(const ull*)&Bs[rb0 + 2 * ASTR + 2 * kp];
            ull b3 = *(const ull*)&Bs[rb0 + 3 * ASTR + 2 * kp];
            ffma2(acc[0][0], a0, b0);
            ffma2(acc[0][1], a0, b1);
            ffma2(acc[0][2], a0, b2);
            ffma2(acc[0][3], a0, b3);
            ffma2(acc[1][0], a1, b0);
            ffma2(acc[1][1], a1, b1);
            ffma2(acc[1][2], a1, b2);
            ffma2(acc[1][3], a1, b3);
        }
        __syncthreads();
    }

    // Horizontal reduce (lo + hi) and stage through smem (reuse As as [64][33])
#pragma unroll
    for (int i = 0; i < 2; ++i)
#pragma unroll
        for (int j = 0; j < 4; ++j) {
            unsigned lo = (unsigned)(acc[i][j] & 0xffffffffull);
            unsigned hi = (unsigned)(acc[i][j] >> 32);
            float s = __uint_as_float(lo) + __uint_as_float(hi);
            As[(ty * 2 + i) * 33 + (tx * 4 + j)] = s;
        }
    __syncthreads();

    // Cell update: 512 (b, j) cells per block, 2 per thread
#pragma unroll
    for (int w = 0; w < 2; ++w) {
        int idx = w * NT + tid;        // 0..511
        int m  = idx >> 3;             // 0..63
        int jj = idx & 7;              // 0..7
        int b = m0 + m;
        int j = j0 + jj;
        float gi = As[m * 33 + jj]      + bih[0 * H_ + j] + bhh[0 * H_ + j];
        float gf = As[m * 33 + 8 + jj]  + bih[1 * H_ + j] + bhh[1 * H_ + j];
        float gg = As[m * 33 + 16 + jj] + bih[2 * H_ + j] + bhh[2 * H_ + j];
        float go = As[m * 33 + 24 + jj] + bih[3 * H_ + j] + bhh[3 * H_ + j];
        float c_old = c[b * H_ + j];
        float cn = sigf(gf) * c_old + sigf(gi) * tanhf(gg);
        float hn = sigf(go) * tanhf(cn);
        c[b * H_ + j]     = cn;
        h_out[b * H_ + j] = hn;
    }
}

// ---------------- zero-init h and c ----------------
__global__ void zero_kernel(float* __restrict__ h, float* __restrict__ c)
{
    int idx = blockIdx.x * blockDim.x + threadIdx.x;
    if (idx < B_ * H_) { h[idx] = 0.0f; c[idx] = 0.0f; }
}

// ---------------- VAE: mean / log_var / z ----------------
__global__ void vae_kernel(const float* __restrict__ h,
                           const float* __restrict__ Wm, const float* __restrict__ bm,
                           const float* __restrict__ Wv, const float* __restrict__ bv,
                           const float* __restrict__ eps,
                           float* __restrict__ out_mean, float* __restrict__ out_lv,
                           float* __restrict__ z)
{
    int w    = (blockIdx.x * blockDim.x + threadIdx.x) >> 5;
    int lane = threadIdx.x & 31;
    if (w >= B_ * L_) return;
    int b = w >> 6, l = w & 63;
    const float* hb = h + b * H_;
    const float* wm = Wm + l * H_;
    const float* wv = Wv + l * H_;
    float sm = 0.0f, sv = 0.0f;
#pragma unroll 4
    for (int k = lane; k < H_; k += 32) {
        float hv = hb[k];
        sm += hv * wm[k];
        sv += hv * wv[k];
    }
#pragma unroll
    for (int o = 16; o > 0; o >>= 1) {
        sm += __shfl_down_sync(0xffffffffu, sm, o);
        sv += __shfl_down_sync(0xffffffffu, sv, o);
    }
    if (lane == 0) {
        sm += bm[l];
        sv += bv[l];
        out_mean[b * L_ + l] = sm;
        out_lv  [b * L_ + l] = sv;
        z[b * L_ + l] = sm + eps[b * L_ + l] * expf(0.5f * sv);
    }
}

// ---------------- decoder init: h0 = z @ W_init^T + b_init; c = 0; x0 = 0 ----------------
__global__ void init_dec(const float* __restrict__ z,
                         const float* __restrict__ Wi, const float* __restrict__ bi,
                         float* __restrict__ h, float* __restrict__ c, float* __restrict__ x)
{
    int idx = blockIdx.x * blockDim.x + threadIdx.x;   // 0..65535
    if (idx >= B_ * H_) return;
    int b = idx >> 9, j = idx & 511;
    const float* zb = z + b * L_;
    const float* wr = Wi + j * L_;
    float s = bi[j];
#pragma unroll 16
    for (int k = 0; k < L_; ++k) s += zb[k] * wr[k];
    h[idx] = s;
    c[idx] = 0.0f;
    if (j < L_) x[b * L_ + j] = 0.0f;
}

// ---------------- decoder output projection: x_hat = h @ W_out^T + b_out ----------------
__global__ void out_proj(const float* __restrict__ h,
                         const float* __restrict__ Wo, const float* __restrict__ bo,
                         float* __restrict__ xbuf, float* __restrict__ out_xhat, int s)
{
    int w    = (blockIdx.x * blockDim.x + threadIdx.x) >> 5;
    int lane = threadIdx.x & 31;
    if (w >= B_ * I_) return;
    int b = w >> 6, i = w & 63;
    const float* hb = h + b * H_;
    const float* wr = Wo + i * H_;
    float sum = 0.0f;
#pragma unroll 4
    for (int k = lane; k < H_; k += 32) sum += hb[k] * wr[k];
#pragma unroll
    for (int o = 16; o > 0; o >>= 1) sum += __shfl_down_sync(0xffffffffu, sum, o);
    if (lane == 0) {
        float v = sum + bo[i];
        xbuf[b * I_ + i] = v;
        out_xhat[(b * DEC_ + s) * I_ + i] = v;
    }
}

// ---------------- launch ----------------
extern "C" void kernel_launch(void* const* d_in, const int* in_sizes, int n_in,
                              void* d_out, int out_size)
{
    (void)in_sizes; (void)n_in; (void)out_size;

    const float* seq    = (const float*)d_in[0];
    // d_in[1] = seq_lengths (unused by reference)
    const float* eps    = (const float*)d_in[2];
    const float* Wih_e  = (const float*)d_in[3];
    const float* Whh_e  = (const float*)d_in[4];
    const float* bih_e  = (const float*)d_in[5];
    const float* bhh_e  = (const float*)d_in[6];
    const float* Wm     = (const float*)d_in[7];
    const float* bm     = (const float*)d_in[8];
    const float* Wv     = (const float*)d_in[9];
    const float* bv     = (const float*)d_in[10];
    const float* Wi     = (const float*)d_in[11];
    const float* bi     = (const float*)d_in[12];
    const float* Wih_d  = (const float*)d_in[13];
    const float* Whh_d  = (const float*)d_in[14];
    const float* bih_d  = (const float*)d_in[15];
    const float* bhh_d  = (const float*)d_in[16];
    const float* Wo     = (const float*)d_in[17];
    const float* bo     = (const float*)d_in[18];

    float* out       = (float*)d_out;
    float* out_xhat  = out;                         // [B, 100, I]
    float* out_mean  = out + B_ * DEC_ * I_;        // [B, L]
    float* out_lv    = out_mean + B_ * L_;          // [B, L]

    float *hA, *hB, *cptr, *zptr, *xptr;
    cudaGetSymbolAddress((void**)&hA,   g_hA);
    cudaGetSymbolAddress((void**)&hB,   g_hB);
    cudaGetSymbolAddress((void**)&cptr, g_c);
    cudaGetSymbolAddress((void**)&zptr, g_z);
    cudaGetSymbolAddress((void**)&xptr, g_x);

    dim3 sgrid(H_ / BJ, B_ / BM);   // (64, 2) = 128 blocks

    // ---- encoder ----
    zero_kernel<<<(B_ * H_ + 255) / 256, 256>>>(hA, cptr);
    const float* hin = hA;
    float*       hout = hB;
    for (int t = 0; t < T_; ++t) {
        lstm_step<<<sgrid, NT>>>(seq + t * I_, T_ * I_,
                                 Wih_e, Whh_e, bih_e, bhh_e,
                                 hin, hout, cptr);
        const float* tmp = hin; hin = hout; hout = (float*)tmp;
    }
    // final h_n is in `hin`

    // ---- VAE ----
    vae_kernel<<<(B_ * L_ * 32) / 256, 256>>>(hin, Wm, bm, Wv, bv, eps,
                                              out_mean, out_lv, zptr);

    // ---- decoder init ----
    init_dec<<<(B_ * H_ + 255) / 256, 256>>>(zptr, Wi, bi, hA, cptr, xptr);

    // ---- decoder loop ----
    hin = hA; hout = hB;
    for (int s = 0; s < DEC_; ++s) {
        lstm_step<<<sgrid, NT>>>(xptr, I_,
                                 Wih_d, Whh_d, bih_d, bhh_d,
                                 hin, hout, cptr);
        out_proj<<<(B_ * I_ * 32) / 256, 256>>>(hout, Wo, bo, xptr, out_xhat, s);
        const float* tmp = hin; hin = hout; hout = (float*)tmp;
    }
}